// round 2
// baseline (speedup 1.0000x reference)
#include <cuda_runtime.h>
#include <cuda_fp16.h>
#include <cooperative_groups.h>

namespace cg = cooperative_groups;

// Problem constants
constexpr int Bc = 8;
constexpr int Nc = 512;
constexpr int Dc = 256;
constexpr int Mc = 32;
constexpr float EPS = 1e-4f;
constexpr int NIT = 48;      // converged far beyond reference's 100 log-domain iters

// Sinkhorn kernel config
constexpr int CSZ = 8;           // cluster size (CTAs per batch)
constexpr int RPC = Nc / CSZ;    // rows per CTA = 64
constexpr int TPB = 512;         // threads per block (16 warps)

// ---------------- scratch (device globals; no allocation allowed) ----------------
__device__ float  g_a[Bc * Nc * Mc];
__device__ float  g_b[Bc * Nc * Mc];
__device__ float  g_C[(size_t)Bc * Nc * Nc];          // 8 MB fp32 cost
__device__ __half g_Kp[(size_t)Bc * Nc * Nc];         // 4 MB fp16: K - 1
__device__ float  g_sumC[Bc];
__device__ unsigned char g_mask[Bc * Nc];

// ---------------- K0: normalize mask dtype (bool bytes vs int32) -----------------
// Reads ONLY the first B*N bytes for detection (valid under both layouts).
// int32 layout: bytes at offset i%4 != 0 are all zero. bool layout: random 0/1
// bytes everywhere -> some nonzero byte at i%4!=0 with overwhelming probability.
__global__ void k_mask(const unsigned char* __restrict__ mraw)
{
    __shared__ int isBool;
    int tid = threadIdx.x;
    if (tid == 0) isBool = 0;
    if (tid < Bc) g_sumC[tid] = 0.f;
    __syncthreads();
    int any = 0;
    for (int i = tid; i < Bc * Nc; i += blockDim.x)
        if ((i & 3) && mraw[i]) any = 1;
    if (any) atomicOr(&isBool, 1);
    __syncthreads();
    if (isBool) {
        for (int i = tid; i < Bc * Nc; i += blockDim.x)
            g_mask[i] = mraw[i] ? 1 : 0;
    } else {
        const int* mi = (const int*)mraw;
        for (int i = tid; i < Bc * Nc; i += blockDim.x)
            g_mask[i] = (mi[i] != 0) ? 1 : 0;
    }
}

// ---------------- K1: projections a = (out+pos)@Wout+bout ; b = sel(in)@Win+bin --
__global__ void k_ab(const float* __restrict__ ein,
                     const float* __restrict__ eout, const float* __restrict__ pad,
                     const float* __restrict__ pos, const float* __restrict__ Win,
                     const float* __restrict__ bin, const float* __restrict__ Wout,
                     const float* __restrict__ bout)
{
    int bn = blockIdx.x;             // 0..B*N-1
    int n  = bn & (Nc - 1);
    __shared__ float s_in[Dc], s_out[Dc];
    __shared__ float red_a[8][Mc], red_b[8][Mc];
    int tid = threadIdx.x;           // 256 == Dc

    bool pm = g_mask[bn] != 0;
    {
        int d = tid;
        s_in[d]  = pm ? pad[d] : ein[(size_t)bn * Dc + d];
        s_out[d] = eout[(size_t)bn * Dc + d] + pos[n * Dc + d];
    }
    __syncthreads();

    int m = tid & 31, seg = tid >> 5;     // 8 segments of 32 d's
    float pa = 0.f, pb = 0.f;
    int d0 = seg * 32;
#pragma unroll
    for (int dd = 0; dd < 32; dd++) {
        int d = d0 + dd;
        pa += s_out[d] * Wout[d * Mc + m];
        pb += s_in[d]  * Win [d * Mc + m];
    }
    red_a[seg][m] = pa; red_b[seg][m] = pb;
    __syncthreads();
    if (seg == 0) {
        float sa = bout[m], sb = bin[m];
#pragma unroll
        for (int s = 0; s < 8; s++) { sa += red_a[s][m]; sb += red_b[s][m]; }
        g_a[(size_t)bn * Mc + m] = sa;
        g_b[(size_t)bn * Mc + m] = sb;
    }
}

// ---------------- K2: C[b,i,j] = sum_m |a[i,m]-b[j,m]| ; per-batch sum -----------
__global__ void k_cost()
{
    int b  = blockIdx.z;
    int i0 = blockIdx.y * 32;
    int j0 = blockIdx.x * 32;
    __shared__ float a_s[32][33], b_s[32][33];
    int tid = threadIdx.x;            // 256
    for (int idx = tid; idx < 1024; idx += 256) {
        int r = idx >> 5, m = idx & 31;
        a_s[r][m] = g_a[((size_t)b * Nc + i0 + r) * Mc + m];
        b_s[r][m] = g_b[((size_t)b * Nc + j0 + r) * Mc + m];
    }
    __syncthreads();

    int j = tid & 31, ig = tid >> 5;  // each thread: 4 rows {ig, ig+8, ig+16, ig+24}, col j
    float acc0 = 0.f, acc1 = 0.f, acc2 = 0.f, acc3 = 0.f;
#pragma unroll
    for (int m = 0; m < 32; m++) {
        float bv = b_s[j][m];
        acc0 += fabsf(a_s[ig     ][m] - bv);
        acc1 += fabsf(a_s[ig +  8][m] - bv);
        acc2 += fabsf(a_s[ig + 16][m] - bv);
        acc3 += fabsf(a_s[ig + 24][m] - bv);
    }
    size_t base = ((size_t)b * Nc + i0) * Nc + j0 + j;
    g_C[base + (size_t)(ig     ) * Nc] = acc0;
    g_C[base + (size_t)(ig +  8) * Nc] = acc1;
    g_C[base + (size_t)(ig + 16) * Nc] = acc2;
    g_C[base + (size_t)(ig + 24) * Nc] = acc3;

    float lsum = acc0 + acc1 + acc2 + acc3;
    lsum += __shfl_xor_sync(0xffffffffu, lsum, 16);
    lsum += __shfl_xor_sync(0xffffffffu, lsum, 8);
    lsum += __shfl_xor_sync(0xffffffffu, lsum, 4);
    lsum += __shfl_xor_sync(0xffffffffu, lsum, 2);
    lsum += __shfl_xor_sync(0xffffffffu, lsum, 1);
    __shared__ float wsum[8];
    if ((tid & 31) == 0) wsum[tid >> 5] = lsum;
    __syncthreads();
    if (tid == 0) {
        float s = 0.f;
#pragma unroll
        for (int w = 0; w < 8; w++) s += wsum[w];
        atomicAdd(&g_sumC[b], s);
    }
}

// ---------------- K3: Kp = exp(-C/(eps*sumC)) - 1  (fp16) ------------------------
__global__ void k_kp()
{
    size_t idx = ((size_t)blockIdx.x * blockDim.x + threadIdx.x) * 4;   // N*N %4==0
    int b = (int)(idx / ((size_t)Nc * Nc));
    float inv = 1.f / (EPS * g_sumC[b]);
    float4 c4 = *(const float4*)(g_C + idx);
    float k0 = __expf(-c4.x * inv) - 1.f;
    float k1 = __expf(-c4.y * inv) - 1.f;
    float k2 = __expf(-c4.z * inv) - 1.f;
    float k3 = __expf(-c4.w * inv) - 1.f;
    __half2* dst = (__half2*)(g_Kp + idx);
    dst[0] = __floats2half2_rn(k0, k1);
    dst[1] = __floats2half2_rn(k2, k3);
}

// ---------------- K4: linear-domain Sinkhorn, K resident in SMEM -----------------
struct SmemLayout {
    __half Ks[RPC * Nc];     // 64 KB : this CTA's 64 rows of (K-1)
    float  c_s[Nc];          // full column scaling vector
    float  z_s[Nc];          // this CTA's column partials
    float  r_s[RPC];         // row scalings for owned rows
    float  zsum[RPC];        // reduction scratch (owned column chunk)
    float  cbuf[RPC];        // new c values for owned chunk
    float  wred[16];
    float  misc[4];          // [0] = S_c = sum(c)
};

__device__ __forceinline__ float warp_sum(float v) {
    v += __shfl_xor_sync(0xffffffffu, v, 16);
    v += __shfl_xor_sync(0xffffffffu, v, 8);
    v += __shfl_xor_sync(0xffffffffu, v, 4);
    v += __shfl_xor_sync(0xffffffffu, v, 2);
    v += __shfl_xor_sync(0xffffffffu, v, 1);
    return v;
}

extern __shared__ char dynsmem[];

__global__ void __cluster_dims__(CSZ, 1, 1) __launch_bounds__(TPB, 1)
k_sinkhorn(float* __restrict__ out)
{
    cg::cluster_group cluster = cg::this_cluster();
    unsigned rank = cluster.block_rank();
    int b = blockIdx.x / CSZ;
    SmemLayout* s = (SmemLayout*)dynsmem;

    int tid  = threadIdx.x;
    int lane = tid & 31;
    int w    = tid >> 5;          // 16 warps

    // Load this CTA's 64x512 fp16 K-slab (64 KB), linear int4 copy
    {
        const int4* src = (const int4*)(g_Kp + (size_t)b * Nc * Nc + (size_t)rank * RPC * Nc);
        int4* dst = (int4*)s->Ks;
#pragma unroll
        for (int t = tid; t < RPC * Nc * 2 / 16; t += TPB) dst[t] = src[t];
    }
    s->c_s[tid] = 1.0f;                  // c0 = exp(v0=0) = 1
    if (tid == 0) s->misc[0] = (float)Nc;
    __syncthreads();

    const float inv_n = 1.0f / (float)Nc;
    const __half2* Ks2 = (const __half2*)s->Ks;

    for (int it = 0; it < NIT; it++) {
        float S_c = s->misc[0];

        // ---- Phase A (row update): r_i = (1/n) / (S_c + sum_j Kp[i,j] c_j) ----
        float2 cf[8];
        {
            const float2* c2 = (const float2*)s->c_s;
#pragma unroll
            for (int k = 0; k < 8; k++) cf[k] = c2[lane + 32 * k];
        }
#pragma unroll
        for (int rr = 0; rr < 4; rr++) {
            int row = w * 4 + rr;
            const __half2* kr = Ks2 + row * (Nc / 2);
            float y = 0.f;
#pragma unroll
            for (int k = 0; k < 8; k++) {
                float2 kf = __half22float2(kr[lane + 32 * k]);
                y += kf.x * cf[k].x + kf.y * cf[k].y;
            }
            y = warp_sum(y);
            if (lane == 0) s->r_s[row] = inv_n / (S_c + y);
        }
        __syncthreads();

        // R_part = sum of this CTA's r
        float rp = s->r_s[lane] + s->r_s[lane + 32];
        rp = warp_sum(rp);

        // ---- Phase B (column partials): z_j = R_part + sum_i Kp[i,j] r_i ----
        {
            int j = w * 32 + lane;
            float z0 = 0.f, z1 = 0.f, z2 = 0.f, z3 = 0.f;
#pragma unroll
            for (int i = 0; i < RPC; i += 4) {
                z0 += (float)s->Ks[(i + 0) * Nc + j] * s->r_s[i + 0];
                z1 += (float)s->Ks[(i + 1) * Nc + j] * s->r_s[i + 1];
                z2 += (float)s->Ks[(i + 2) * Nc + j] * s->r_s[i + 2];
                z3 += (float)s->Ks[(i + 3) * Nc + j] * s->r_s[i + 3];
            }
            s->z_s[j] = (z0 + z1) + (z2 + z3) + rp;
        }
        cluster.sync();   // all CTAs' z partials visible

        // ---- cross-CTA reduce of owned column chunk [rank*64, rank*64+64) ----
        int jl   = tid & 63;        // column within chunk
        int srcR = tid >> 6;        // which CTA's partial
        int jg   = rank * RPC + jl; // global column
        float* remote_z = cluster.map_shared_rank(s->z_s, srcR);
        float val = remote_z[jg];
        if (tid < RPC) s->zsum[tid] = 0.f;
        __syncthreads();
        atomicAdd(&s->zsum[jl], val);
        __syncthreads();
        if (tid < RPC) s->cbuf[tid] = inv_n / s->zsum[tid];
        __syncthreads();

        // ---- broadcast new c chunk to every CTA in cluster ----
        {
            int dstR = tid >> 6;
            float* remote_c = cluster.map_shared_rank(s->c_s, dstR);
            remote_c[jg] = s->cbuf[jl];
        }
        cluster.sync();   // full c vector updated everywhere

        // ---- S_c = sum(c) ----
        float sc = warp_sum(s->c_s[tid]);
        if (lane == 0) s->wred[w] = sc;
        __syncthreads();
        if (tid == 0) {
            float acc = 0.f;
#pragma unroll
            for (int k = 0; k < 16; k++) acc += s->wred[k];
            s->misc[0] = acc;
        }
        __syncthreads();
    }

    // ---- epilogue: P[b,i,j] = (1 + Kp[i,j]) * r_i * c_j ----
    float* Ob = out + (size_t)b * Nc * Nc + (size_t)rank * RPC * Nc;
#pragma unroll
    for (int rr = 0; rr < 4; rr++) {
        int row = w * 4 + rr;
        float rv = s->r_s[row];
        float* orow = Ob + (size_t)row * Nc;
#pragma unroll
        for (int k = 0; k < 16; k++) {
            int j = lane + 32 * k;
            orow[j] = (1.0f + (float)s->Ks[row * Nc + j]) * rv * s->c_s[j];
        }
    }
}

// ---------------- launcher -------------------------------------------------------
extern "C" void kernel_launch(void* const* d_in, const int* in_sizes, int n_in,
                              void* d_out, int out_size)
{
    const float*         ein  = (const float*)d_in[0];
    const unsigned char* mraw = (const unsigned char*)d_in[1];   // bool OR int32, sniffed
    const float*         eout = (const float*)d_in[2];
    const float*         pad  = (const float*)d_in[3];
    const float*         pos  = (const float*)d_in[4];
    const float*         Win  = (const float*)d_in[5];
    const float*         bin  = (const float*)d_in[6];
    const float*         Wout = (const float*)d_in[7];
    const float*         bout = (const float*)d_in[8];
    float* out = (float*)d_out;

    k_mask<<<1, 512>>>(mraw);

    k_ab<<<Bc * Nc, 256>>>(ein, eout, pad, pos, Win, bin, Wout, bout);

    dim3 g2(Nc / 32, Nc / 32, Bc);
    k_cost<<<g2, 256>>>();

    k_kp<<<(Bc * Nc * Nc) / (4 * 256), 256>>>();

    cudaFuncSetAttribute(k_sinkhorn, cudaFuncAttributeMaxDynamicSharedMemorySize,
                         (int)sizeof(SmemLayout));
    k_sinkhorn<<<Bc * CSZ, TPB, sizeof(SmemLayout)>>>(out);
}

// round 4
// speedup vs baseline: 2.5799x; 2.5799x over previous
#include <cuda_runtime.h>
#include <cuda_fp16.h>
#include <cooperative_groups.h>

namespace cg = cooperative_groups;

// Problem constants
constexpr int Bc = 8;
constexpr int Nc = 512;
constexpr int Dc = 256;
constexpr int Mc = 32;
constexpr float EPS = 1e-4f;
constexpr int NIT = 10;      // kappa <= ~0.012 -> converged to fp32 noise in <8 iters

// Sinkhorn kernel config
constexpr int CSZ = 8;           // cluster size (CTAs per batch)
constexpr int RPC = Nc / CSZ;    // rows per CTA = 64
constexpr int TPB = 512;         // threads per block (16 warps)

// ---------------- scratch (device globals; no allocation allowed) ----------------
__device__ float  g_a[Bc * Nc * Mc];
__device__ float  g_b[Bc * Nc * Mc];
__device__ float  g_C[(size_t)Bc * Nc * Nc];          // 8 MB fp32 cost
__device__ __half g_Kp[(size_t)Bc * Nc * Nc];         // 4 MB fp16: K - 1, row-major
__device__ __half g_KpT[(size_t)Bc * Nc * Nc];        // 4 MB fp16: K - 1, transposed
__device__ float  g_sumC[Bc];
__device__ unsigned char g_mask[Bc * Nc];

// ---------------- K0: normalize mask dtype (bool bytes vs int32) -----------------
__global__ void k_mask(const unsigned char* __restrict__ mraw)
{
    __shared__ int isBool;
    int tid = threadIdx.x;
    if (tid == 0) isBool = 0;
    if (tid < Bc) g_sumC[tid] = 0.f;
    __syncthreads();
    int any = 0;
    for (int i = tid; i < Bc * Nc; i += blockDim.x)
        if ((i & 3) && mraw[i]) any = 1;
    if (any) atomicOr(&isBool, 1);
    __syncthreads();
    if (isBool) {
        for (int i = tid; i < Bc * Nc; i += blockDim.x)
            g_mask[i] = mraw[i] ? 1 : 0;
    } else {
        const int* mi = (const int*)mraw;
        for (int i = tid; i < Bc * Nc; i += blockDim.x)
            g_mask[i] = (mi[i] != 0) ? 1 : 0;
    }
}

// ---------------- K1: projections a = (out+pos)@Wout+bout ; b = sel(in)@Win+bin --
__global__ void k_ab(const float* __restrict__ ein,
                     const float* __restrict__ eout, const float* __restrict__ pad,
                     const float* __restrict__ pos, const float* __restrict__ Win,
                     const float* __restrict__ bin, const float* __restrict__ Wout,
                     const float* __restrict__ bout)
{
    int bn = blockIdx.x;             // 0..B*N-1
    int n  = bn & (Nc - 1);
    __shared__ float s_in[Dc], s_out[Dc];
    __shared__ float red_a[8][Mc], red_b[8][Mc];
    int tid = threadIdx.x;           // 256 == Dc

    bool pm = g_mask[bn] != 0;
    {
        int d = tid;
        s_in[d]  = pm ? pad[d] : ein[(size_t)bn * Dc + d];
        s_out[d] = eout[(size_t)bn * Dc + d] + pos[n * Dc + d];
    }
    __syncthreads();

    int m = tid & 31, seg = tid >> 5;     // 8 segments of 32 d's
    float pa = 0.f, pb = 0.f;
    int d0 = seg * 32;
#pragma unroll
    for (int dd = 0; dd < 32; dd++) {
        int d = d0 + dd;
        pa += s_out[d] * Wout[d * Mc + m];
        pb += s_in[d]  * Win [d * Mc + m];
    }
    red_a[seg][m] = pa; red_b[seg][m] = pb;
    __syncthreads();
    if (seg == 0) {
        float sa = bout[m], sb = bin[m];
#pragma unroll
        for (int s = 0; s < 8; s++) { sa += red_a[s][m]; sb += red_b[s][m]; }
        g_a[(size_t)bn * Mc + m] = sa;
        g_b[(size_t)bn * Mc + m] = sb;
    }
}

// ---------------- K2: C[b,i,j] = sum_m |a[i,m]-b[j,m]| ; per-batch sum -----------
__global__ void k_cost()
{
    int b  = blockIdx.z;
    int i0 = blockIdx.y * 32;
    int j0 = blockIdx.x * 32;
    __shared__ float a_s[32][33], b_s[32][33];
    int tid = threadIdx.x;            // 256
    for (int idx = tid; idx < 1024; idx += 256) {
        int r = idx >> 5, m = idx & 31;
        a_s[r][m] = g_a[((size_t)b * Nc + i0 + r) * Mc + m];
        b_s[r][m] = g_b[((size_t)b * Nc + j0 + r) * Mc + m];
    }
    __syncthreads();

    int j = tid & 31, ig = tid >> 5;  // each thread: 4 rows {ig, ig+8, ig+16, ig+24}, col j
    float acc0 = 0.f, acc1 = 0.f, acc2 = 0.f, acc3 = 0.f;
#pragma unroll
    for (int m = 0; m < 32; m++) {
        float bv = b_s[j][m];
        acc0 += fabsf(a_s[ig     ][m] - bv);
        acc1 += fabsf(a_s[ig +  8][m] - bv);
        acc2 += fabsf(a_s[ig + 16][m] - bv);
        acc3 += fabsf(a_s[ig + 24][m] - bv);
    }
    size_t base = ((size_t)b * Nc + i0) * Nc + j0 + j;
    g_C[base + (size_t)(ig     ) * Nc] = acc0;
    g_C[base + (size_t)(ig +  8) * Nc] = acc1;
    g_C[base + (size_t)(ig + 16) * Nc] = acc2;
    g_C[base + (size_t)(ig + 24) * Nc] = acc3;

    float lsum = acc0 + acc1 + acc2 + acc3;
    lsum += __shfl_xor_sync(0xffffffffu, lsum, 16);
    lsum += __shfl_xor_sync(0xffffffffu, lsum, 8);
    lsum += __shfl_xor_sync(0xffffffffu, lsum, 4);
    lsum += __shfl_xor_sync(0xffffffffu, lsum, 2);
    lsum += __shfl_xor_sync(0xffffffffu, lsum, 1);
    __shared__ float wsum[8];
    if ((tid & 31) == 0) wsum[tid >> 5] = lsum;
    __syncthreads();
    if (tid == 0) {
        float s = 0.f;
#pragma unroll
        for (int w = 0; w < 8; w++) s += wsum[w];
        atomicAdd(&g_sumC[b], s);
    }
}

// ---------------- K3: Kp = exp(-C/(eps*sumC)) - 1, both row-major and transposed -
// grid (Nc/64, Nc/64, Bc), block 256. 64x64 tile; smem transpose for g_KpT.
__global__ void k_kp()
{
    int b  = blockIdx.z;
    int i0 = blockIdx.y * 64;
    int j0 = blockIdx.x * 64;
    __shared__ __half tile[64][66];   // [col][row], pad -> conflict-light
    int tid = threadIdx.x;
    float inv = 1.f / (EPS * g_sumC[b]);

#pragma unroll
    for (int k = 0; k < 8; k++) {
        int e = (tid + k * 256) * 2;          // 0..8190, even
        int r = e >> 6, c = e & 63;
        float2 c2 = *(const float2*)&g_C[((size_t)b * Nc + i0 + r) * Nc + j0 + c];
        __half h0 = __float2half_rn(__expf(-c2.x * inv) - 1.f);
        __half h1 = __float2half_rn(__expf(-c2.y * inv) - 1.f);
        *(__half2*)&g_Kp[((size_t)b * Nc + i0 + r) * Nc + j0 + c] = __halves2half2(h0, h1);
        tile[c][r]     = h0;
        tile[c + 1][r] = h1;
    }
    __syncthreads();
#pragma unroll
    for (int k = 0; k < 8; k++) {
        int e  = (tid + k * 256) * 2;
        int jl = e >> 6, il = e & 63;
        __half2 v = __halves2half2(tile[jl][il], tile[jl][il + 1]);
        *(__half2*)&g_KpT[((size_t)b * Nc + j0 + jl) * Nc + i0 + il] = v;
    }
}

// ---------------- K4: linear-domain Sinkhorn, K + K^T resident in SMEM -----------
struct SmemLayout {
    __half Ks [RPC * Nc];    // 64 KB : this CTA's 64 rows of (K-1)
    __half KsT[RPC * Nc];    // 64 KB : this CTA's 64 COLUMNS of (K-1), row-major in col idx
    float  c_s[Nc];          // full column scaling vector
    float  r_s[Nc];          // full row scaling vector
    float  r_own[RPC];
    float  c_own[RPC];
    float  wredA[16];
    float  wredB[16];
};

__device__ __forceinline__ float warp_sum(float v) {
    v += __shfl_xor_sync(0xffffffffu, v, 16);
    v += __shfl_xor_sync(0xffffffffu, v, 8);
    v += __shfl_xor_sync(0xffffffffu, v, 4);
    v += __shfl_xor_sync(0xffffffffu, v, 2);
    v += __shfl_xor_sync(0xffffffffu, v, 1);
    return v;
}

extern __shared__ char dynsmem[];

// 4-row half2 matvec: out[row] = inv_n / (S + sum_j slab[row][j]*vec[j])
__device__ __forceinline__ void matvec4(const __half2* __restrict__ slab2,
                                        const float* __restrict__ vec,
                                        float* __restrict__ outv,
                                        float S, float inv_n, int w, int lane)
{
    float2 vf[8];
    const float2* v2 = (const float2*)vec;
#pragma unroll
    for (int k = 0; k < 8; k++) vf[k] = v2[lane + 32 * k];
#pragma unroll
    for (int rr = 0; rr < 4; rr++) {
        int row = w * 4 + rr;
        const __half2* kr = slab2 + row * (Nc / 2);
        float y = 0.f;
#pragma unroll
        for (int k = 0; k < 8; k++) {
            float2 kf = __half22float2(kr[lane + 32 * k]);
            y += kf.x * vf[k].x + kf.y * vf[k].y;
        }
        y = warp_sum(y);
        if (lane == 0) outv[row] = inv_n / (S + y);
    }
}

__global__ void __cluster_dims__(CSZ, 1, 1) __launch_bounds__(TPB, 1)
k_sinkhorn(float* __restrict__ out)
{
    cg::cluster_group cluster = cg::this_cluster();
    unsigned rank = cluster.block_rank();
    int b = blockIdx.x / CSZ;
    SmemLayout* s = (SmemLayout*)dynsmem;

    int tid  = threadIdx.x;
    int lane = tid & 31;
    int w    = tid >> 5;          // 16 warps
    int jl   = tid & 63;          // column-within-chunk for exchange
    int dstR = tid >> 6;          // destination rank for exchange

    // Load row slab + column slab (64 KB each), linear int4 copies
    {
        const int4* srcR_ = (const int4*)(g_Kp  + ((size_t)b * Nc + rank * RPC) * Nc);
        const int4* srcT  = (const int4*)(g_KpT + ((size_t)b * Nc + rank * RPC) * Nc);
        int4* dR = (int4*)s->Ks;
        int4* dT = (int4*)s->KsT;
#pragma unroll
        for (int t = tid; t < RPC * Nc * 2 / 16; t += TPB) { dR[t] = srcR_[t]; dT[t] = srcT[t]; }
    }
    s->c_s[tid] = 1.0f;                  // c0 = 1
    __syncthreads();

    const float inv_n = 1.0f / (float)Nc;
    const __half2* Ks2  = (const __half2*)s->Ks;
    const __half2* KsT2 = (const __half2*)s->KsT;
    float S_c = (float)Nc;

    float* remote_r = (float*)cluster.map_shared_rank(s->r_s, dstR) + rank * RPC + jl;
    float* remote_c = (float*)cluster.map_shared_rank(s->c_s, dstR) + rank * RPC + jl;

    for (int it = 0; it < NIT; it++) {
        // ---- Phase A: r_own = inv_n / (S_c + Kp_rows . c) ----
        matvec4(Ks2, s->c_s, s->r_own, S_c, inv_n, w, lane);
        __syncthreads();

        // broadcast r_own -> every rank's full r_s
        *remote_r = s->r_own[jl];
        cluster.sync();

        // S_r = sum(r_s)
        { float v = warp_sum(s->r_s[tid]); if (lane == 0) s->wredA[w] = v; }
        __syncthreads();
        float S_r = 0.f;
#pragma unroll
        for (int k = 0; k < 16; k++) S_r += s->wredA[k];

        // ---- Phase B: c_own = inv_n / (S_r + Kp_cols . r) ----
        matvec4(KsT2, s->r_s, s->c_own, S_r, inv_n, w, lane);
        __syncthreads();

        // broadcast c_own -> every rank's full c_s
        *remote_c = s->c_own[jl];
        cluster.sync();

        // S_c = sum(c_s)
        { float v = warp_sum(s->c_s[tid]); if (lane == 0) s->wredB[w] = v; }
        __syncthreads();
        S_c = 0.f;
#pragma unroll
        for (int k = 0; k < 16; k++) S_c += s->wredB[k];
    }

    // ---- epilogue: P[b,i,j] = (1 + Kp[i,j]) * r_i * c_j ----
    float* Ob = out + ((size_t)b * Nc + rank * RPC) * Nc;
#pragma unroll
    for (int rr = 0; rr < 4; rr++) {
        int row = w * 4 + rr;
        float rv = s->r_own[row];
        float* orow = Ob + (size_t)row * Nc;
        const __half2* kr = (const __half2*)s->Ks + row * (Nc / 2);
        const float2* c2 = (const float2*)s->c_s;
#pragma unroll
        for (int k = 0; k < 8; k++) {
            float2 kf = __half22float2(kr[lane + 32 * k]);
            float2 cf = c2[lane + 32 * k];
            float2 o;
            o.x = (1.0f + kf.x) * rv * cf.x;
            o.y = (1.0f + kf.y) * rv * cf.y;
            *(float2*)&orow[2 * (lane + 32 * k)] = o;
        }
    }
}

// ---------------- launcher -------------------------------------------------------
extern "C" void kernel_launch(void* const* d_in, const int* in_sizes, int n_in,
                              void* d_out, int out_size)
{
    const float*         ein  = (const float*)d_in[0];
    const unsigned char* mraw = (const unsigned char*)d_in[1];   // bool OR int32, sniffed
    const float*         eout = (const float*)d_in[2];
    const float*         pad  = (const float*)d_in[3];
    const float*         pos  = (const float*)d_in[4];
    const float*         Win  = (const float*)d_in[5];
    const float*         bin  = (const float*)d_in[6];
    const float*         Wout = (const float*)d_in[7];
    const float*         bout = (const float*)d_in[8];
    float* out = (float*)d_out;

    k_mask<<<1, 512>>>(mraw);

    k_ab<<<Bc * Nc, 256>>>(ein, eout, pad, pos, Win, bin, Wout, bout);

    dim3 g2(Nc / 32, Nc / 32, Bc);
    k_cost<<<g2, 256>>>();

    dim3 g3(Nc / 64, Nc / 64, Bc);
    k_kp<<<g3, 256>>>();

    cudaFuncSetAttribute(k_sinkhorn, cudaFuncAttributeMaxDynamicSharedMemorySize,
                         (int)sizeof(SmemLayout));
    k_sinkhorn<<<Bc * CSZ, TPB, sizeof(SmemLayout)>>>(out);
}

// round 5
// speedup vs baseline: 2.8715x; 1.1130x over previous
#include <cuda_runtime.h>
#include <cuda_fp16.h>
#include <cooperative_groups.h>

namespace cg = cooperative_groups;

// Problem constants
constexpr int Bc = 8;
constexpr int Nc = 512;
constexpr int Dc = 256;
constexpr int Mc = 32;
constexpr float EPS = 1e-4f;
constexpr int NIT = 8;       // kappa <= ~0.04 pessimistic -> kappa^8 ~ 6e-12

// Sinkhorn kernel config
constexpr int CSZ = 8;           // cluster size (CTAs per batch)
constexpr int RPC = Nc / CSZ;    // rows per CTA = 64
constexpr int TPB = 512;         // threads per block (16 warps)

// ---------------- scratch (device globals; no allocation allowed) ----------------
__device__ float  g_a[Bc * Nc * Mc];
__device__ float  g_b[Bc * Nc * Mc];
__device__ __half g_Ch [(size_t)Bc * Nc * Nc];        // 4 MB fp16 raw cost, row-major
__device__ __half g_CTh[(size_t)Bc * Nc * Nc];        // 4 MB fp16 raw cost, transposed
__device__ float  g_sumC[Bc];

// ---------------- K1: projections, with inline mask-dtype sniff ------------------
// a = (emb_out + pos) @ W_out + b_out ; b = select(emb_in, pad) @ W_in + b_in
__global__ void k_ab(const float* __restrict__ ein, const unsigned char* __restrict__ mraw,
                     const float* __restrict__ eout, const float* __restrict__ pad,
                     const float* __restrict__ pos, const float* __restrict__ Win,
                     const float* __restrict__ bin, const float* __restrict__ Wout,
                     const float* __restrict__ bout)
{
    int bn = blockIdx.x;             // 0..B*N-1
    int n  = bn & (Nc - 1);
    __shared__ float s_in[Dc], s_out[Dc];
    __shared__ float red_a[8][Mc], red_b[8][Mc];
    __shared__ int s_isBool;
    int tid = threadIdx.x;           // 256 == Dc

    if (tid == 0) s_isBool = 0;
    if (bn < Bc && tid == 0) g_sumC[bn] = 0.f;
    __syncthreads();

    // Sniff: first 256 words (1024 bytes) are valid under both layouts.
    // int32 layout (values 0/1): bytes 1..3 of every word are zero.
    // bool layout: upper bytes carry random 0/1 -> some bit set (p_miss = 2^-768).
    {
        unsigned v = ((const unsigned*)mraw)[tid];
        if (v & 0xFFFFFF00u) atomicOr(&s_isBool, 1);
    }
    __syncthreads();
    bool pm = s_isBool ? (mraw[bn] != 0) : (((const int*)mraw)[bn] != 0);

    {
        int d = tid;
        s_in[d]  = pm ? pad[d] : ein[(size_t)bn * Dc + d];
        s_out[d] = eout[(size_t)bn * Dc + d] + pos[n * Dc + d];
    }
    __syncthreads();

    int m = tid & 31, seg = tid >> 5;     // 8 segments of 32 d's
    float pa = 0.f, pb = 0.f;
    int d0 = seg * 32;
#pragma unroll
    for (int dd = 0; dd < 32; dd++) {
        int d = d0 + dd;
        pa += s_out[d] * Wout[d * Mc + m];
        pb += s_in[d]  * Win [d * Mc + m];
    }
    red_a[seg][m] = pa; red_b[seg][m] = pb;
    __syncthreads();
    if (seg == 0) {
        float sa = bout[m], sb = bin[m];
#pragma unroll
        for (int s = 0; s < 8; s++) { sa += red_a[s][m]; sb += red_b[s][m]; }
        g_a[(size_t)bn * Mc + m] = sa;
        g_b[(size_t)bn * Mc + m] = sb;
    }
}

// ---------------- K2: C[b,i,j] = sum_m |a[i,m]-b[j,m]| -> fp16 C and C^T + sum ---
__global__ void k_cost()
{
    int b  = blockIdx.z;
    int i0 = blockIdx.y * 32;
    int j0 = blockIdx.x * 32;
    __shared__ float a_s[32][33], b_s[32][33], t_s[32][33];
    __shared__ float wsum[8];
    int tid = threadIdx.x;            // 256
    for (int idx = tid; idx < 1024; idx += 256) {
        int r = idx >> 5, m = idx & 31;
        a_s[r][m] = g_a[((size_t)b * Nc + i0 + r) * Mc + m];
        b_s[r][m] = g_b[((size_t)b * Nc + j0 + r) * Mc + m];
    }
    __syncthreads();

    int j = tid & 31, ig = tid >> 5;  // each thread: rows {ig, ig+8, ig+16, ig+24}, col j
    float acc0 = 0.f, acc1 = 0.f, acc2 = 0.f, acc3 = 0.f;
#pragma unroll
    for (int m = 0; m < 32; m++) {
        float bv = b_s[j][m];
        acc0 += fabsf(a_s[ig     ][m] - bv);
        acc1 += fabsf(a_s[ig +  8][m] - bv);
        acc2 += fabsf(a_s[ig + 16][m] - bv);
        acc3 += fabsf(a_s[ig + 24][m] - bv);
    }
    // stage fp32 tile (i-major) for coalesced fp16 writes of both C and C^T
    t_s[ig     ][j] = acc0;
    t_s[ig +  8][j] = acc1;
    t_s[ig + 16][j] = acc2;
    t_s[ig + 24][j] = acc3;

    // per-batch sum reduction
    float lsum = (acc0 + acc1) + (acc2 + acc3);
    lsum += __shfl_xor_sync(0xffffffffu, lsum, 16);
    lsum += __shfl_xor_sync(0xffffffffu, lsum, 8);
    lsum += __shfl_xor_sync(0xffffffffu, lsum, 4);
    lsum += __shfl_xor_sync(0xffffffffu, lsum, 2);
    lsum += __shfl_xor_sync(0xffffffffu, lsum, 1);
    if ((tid & 31) == 0) wsum[tid >> 5] = lsum;
    __syncthreads();
    if (tid == 0) {
        float s = 0.f;
#pragma unroll
        for (int w = 0; w < 8; w++) s += wsum[w];
        atomicAdd(&g_sumC[b], s);
    }

    // write C rows (fp16, 8B per thread) and C^T rows (column reads, pad-33 -> conflict-free)
    int r  = tid >> 3;
    int c0 = (tid & 7) * 4;
    {
        __half2 h01 = __floats2half2_rn(t_s[r][c0],     t_s[r][c0 + 1]);
        __half2 h23 = __floats2half2_rn(t_s[r][c0 + 2], t_s[r][c0 + 3]);
        size_t cb = ((size_t)b * Nc + i0 + r) * Nc + j0 + c0;
        *(__half2*)&g_Ch[cb]     = h01;
        *(__half2*)&g_Ch[cb + 2] = h23;
    }
    {
        __half2 h01 = __floats2half2_rn(t_s[c0][r],     t_s[c0 + 1][r]);
        __half2 h23 = __floats2half2_rn(t_s[c0 + 2][r], t_s[c0 + 3][r]);
        size_t tb = ((size_t)b * Nc + j0 + r) * Nc + i0 + c0;
        *(__half2*)&g_CTh[tb]     = h01;
        *(__half2*)&g_CTh[tb + 2] = h23;
    }
}

// ---------------- K3: linear-domain Sinkhorn, K + K^T resident in SMEM -----------
struct SmemLayout {
    __half Ks [RPC * Nc];    // 64 KB : this CTA's 64 rows of (K-1)   (loaded as C, exp'd in place)
    __half KsT[RPC * Nc];    // 64 KB : this CTA's 64 columns of (K-1) (contiguous after Ks)
    float  c_s[Nc];          // full column scaling vector
    float  r_s[Nc];          // full row scaling vector
    float  r_own[RPC];
    float  c_own[RPC];
    float  wredA[16];
    float  wredB[16];
};

__device__ __forceinline__ float warp_sum(float v) {
    v += __shfl_xor_sync(0xffffffffu, v, 16);
    v += __shfl_xor_sync(0xffffffffu, v, 8);
    v += __shfl_xor_sync(0xffffffffu, v, 4);
    v += __shfl_xor_sync(0xffffffffu, v, 2);
    v += __shfl_xor_sync(0xffffffffu, v, 1);
    return v;
}

extern __shared__ char dynsmem[];

// 4-row half2 matvec: out[row] = inv_n / (S + sum_j slab[row][j]*vec[j])
__device__ __forceinline__ void matvec4(const __half2* __restrict__ slab2,
                                        const float* __restrict__ vec,
                                        float* __restrict__ outv,
                                        float S, float inv_n, int w, int lane)
{
    float2 vf[8];
    const float2* v2 = (const float2*)vec;
#pragma unroll
    for (int k = 0; k < 8; k++) vf[k] = v2[lane + 32 * k];
#pragma unroll
    for (int rr = 0; rr < 4; rr++) {
        int row = w * 4 + rr;
        const __half2* kr = slab2 + row * (Nc / 2);
        float y = 0.f;
#pragma unroll
        for (int k = 0; k < 8; k++) {
            float2 kf = __half22float2(kr[lane + 32 * k]);
            y += kf.x * vf[k].x + kf.y * vf[k].y;
        }
        y = warp_sum(y);
        if (lane == 0) outv[row] = inv_n / (S + y);
    }
}

__global__ void __cluster_dims__(CSZ, 1, 1) __launch_bounds__(TPB, 1)
k_sinkhorn(float* __restrict__ out)
{
    cg::cluster_group cluster = cg::this_cluster();
    unsigned rank = cluster.block_rank();
    int b = blockIdx.x / CSZ;
    SmemLayout* s = (SmemLayout*)dynsmem;

    int tid  = threadIdx.x;
    int lane = tid & 31;
    int w    = tid >> 5;          // 16 warps
    int jl   = tid & 63;          // column-within-chunk for exchange
    int dstR = tid >> 6;          // destination rank for exchange

    // Load raw-C row slab + column slab (64 KB each), linear int4 copies
    {
        const int4* srcR_ = (const int4*)(g_Ch  + ((size_t)b * Nc + rank * RPC) * Nc);
        const int4* srcT  = (const int4*)(g_CTh + ((size_t)b * Nc + rank * RPC) * Nc);
        int4* dR = (int4*)s->Ks;
        int4* dT = (int4*)s->KsT;
#pragma unroll
        for (int t = tid; t < RPC * Nc * 2 / 16; t += TPB) { dR[t] = srcR_[t]; dT[t] = srcT[t]; }
    }
    s->c_s[tid] = 1.0f;                  // c0 = 1
    __syncthreads();

    // In-place convert: Kp = exp(-C * inv) - 1 over both slabs (contiguous)
    {
        float inv = 1.f / (EPS * g_sumC[b]);
        __half2* p = (__half2*)s->Ks;    // Ks + KsT contiguous: 2*RPC*Nc/2 half2
#pragma unroll
        for (int t = tid; t < RPC * Nc; t += TPB) {
            float2 cf = __half22float2(p[t]);
            p[t] = __floats2half2_rn(__expf(-cf.x * inv) - 1.f,
                                     __expf(-cf.y * inv) - 1.f);
        }
    }
    __syncthreads();

    const float inv_n = 1.0f / (float)Nc;
    const __half2* Ks2  = (const __half2*)s->Ks;
    const __half2* KsT2 = (const __half2*)s->KsT;
    float S_c = (float)Nc;

    float* remote_r = (float*)cluster.map_shared_rank(s->r_s, dstR) + rank * RPC + jl;
    float* remote_c = (float*)cluster.map_shared_rank(s->c_s, dstR) + rank * RPC + jl;

    for (int it = 0; it < NIT; it++) {
        // ---- Phase A: r_own = inv_n / (S_c + Kp_rows . c) ----
        matvec4(Ks2, s->c_s, s->r_own, S_c, inv_n, w, lane);
        __syncthreads();

        // broadcast r_own -> every rank's full r_s
        *remote_r = s->r_own[jl];
        cluster.sync();

        // S_r = sum(r_s)
        { float v = warp_sum(s->r_s[tid]); if (lane == 0) s->wredA[w] = v; }
        __syncthreads();
        float S_r = 0.f;
#pragma unroll
        for (int k = 0; k < 16; k++) S_r += s->wredA[k];

        // ---- Phase B: c_own = inv_n / (S_r + Kp_cols . r) ----
        matvec4(KsT2, s->r_s, s->c_own, S_r, inv_n, w, lane);
        __syncthreads();

        // broadcast c_own -> every rank's full c_s
        *remote_c = s->c_own[jl];
        cluster.sync();

        // S_c = sum(c_s)
        { float v = warp_sum(s->c_s[tid]); if (lane == 0) s->wredB[w] = v; }
        __syncthreads();
        S_c = 0.f;
#pragma unroll
        for (int k = 0; k < 16; k++) S_c += s->wredB[k];
    }

    // ---- epilogue: P[b,i,j] = (1 + Kp[i,j]) * r_i * c_j ----
    float* Ob = out + ((size_t)b * Nc + rank * RPC) * Nc;
#pragma unroll
    for (int rr = 0; rr < 4; rr++) {
        int row = w * 4 + rr;
        float rv = s->r_own[row];
        float* orow = Ob + (size_t)row * Nc;
        const __half2* kr = (const __half2*)s->Ks + row * (Nc / 2);
        const float2* c2 = (const float2*)s->c_s;
#pragma unroll
        for (int k = 0; k < 8; k++) {
            float2 kf = __half22float2(kr[lane + 32 * k]);
            float2 cf = c2[lane + 32 * k];
            float2 o;
            o.x = (1.0f + kf.x) * rv * cf.x;
            o.y = (1.0f + kf.y) * rv * cf.y;
            *(float2*)&orow[2 * (lane + 32 * k)] = o;
        }
    }
}

// ---------------- launcher -------------------------------------------------------
extern "C" void kernel_launch(void* const* d_in, const int* in_sizes, int n_in,
                              void* d_out, int out_size)
{
    const float*         ein  = (const float*)d_in[0];
    const unsigned char* mraw = (const unsigned char*)d_in[1];   // bool OR int32, sniffed
    const float*         eout = (const float*)d_in[2];
    const float*         pad  = (const float*)d_in[3];
    const float*         pos  = (const float*)d_in[4];
    const float*         Win  = (const float*)d_in[5];
    const float*         bin  = (const float*)d_in[6];
    const float*         Wout = (const float*)d_in[7];
    const float*         bout = (const float*)d_in[8];
    float* out = (float*)d_out;

    k_ab<<<Bc * Nc, 256>>>(ein, mraw, eout, pad, pos, Win, bin, Wout, bout);

    dim3 g2(Nc / 32, Nc / 32, Bc);
    k_cost<<<g2, 256>>>();

    cudaFuncSetAttribute(k_sinkhorn, cudaFuncAttributeMaxDynamicSharedMemorySize,
                         (int)sizeof(SmemLayout));
    k_sinkhorn<<<Bc * CSZ, TPB, sizeof(SmemLayout)>>>(out);
}